// round 16
// baseline (speedup 1.0000x reference)
#include <cuda_runtime.h>
#include <cuda_bf16.h>
#include <cstdint>

// Problem constants
#define BATCH 64
#define CIN   64
#define H     128
#define W     128
#define HW    (H*W)
#define COUT  256
#define OH    126
#define OW    126
#define MTOT  (OH*OW)     // 15876
#define KTOT  (CIN*9)     // 576
#define NSTG  9           // 9 stages of K=64 (one per (kh,kw))

// Scratch (__device__ globals: allocation-free; zero-initialized pad)
// x in NHWC bf16: g_xn[b][h][w][ci]; +4096 pad covers A-slab overreads (zero-init)
__device__ __align__(16) __nv_bfloat16 g_xn[(size_t)BATCH*H*W*CIN + 4096];
// weights bf16, n-major K-reordered rows: g_wb2[co][k'], k' = (kh*3+kw)*64 + ci
__device__ __align__(16) __nv_bfloat16 g_wb2[COUT*KTOT];

// ---------------- prologue kernels ----------------

__global__ void cvt_nhwc_kernel(const float* __restrict__ x) {
    // direct NCHW->NHWC gather: one block per (h, b); no smem transpose
    const int h = blockIdx.x, b = blockIdx.y, tid = threadIdx.x;
    const float* src = x + (size_t)b * CIN * HW + (size_t)h * W;
    __nv_bfloat16* dst = g_xn + ((size_t)(b * H + h) * W) * CIN;
    #pragma unroll
    for (int i = 0; i < 4; i++) {
        int idx = tid + i * 256;          // 1024 uint4 chunks
        int w = idx >> 3, c0 = (idx & 7) * 8;
        uint32_t r[4];
        #pragma unroll
        for (int j = 0; j < 4; j++) {
            float lo = src[(size_t)(c0 + 2 * j)     * HW + w];
            float hi = src[(size_t)(c0 + 2 * j + 1) * HW + w];
            __nv_bfloat162 p = __floats2bfloat162_rn(lo, hi);
            r[j] = *reinterpret_cast<uint32_t*>(&p);
        }
        *reinterpret_cast<uint4*>(dst + (size_t)w * CIN + c0) =
            make_uint4(r[0], r[1], r[2], r[3]);
    }
}

// weights reorder (n-major rows) + output zero in one launch
__global__ void cvt_w_zero_kernel(const float* __restrict__ w, float* __restrict__ out) {
    const int co = blockIdx.x;     // 0..255
    const int t  = threadIdx.x;    // 0..63 (= ci)
    #pragma unroll
    for (int j = 0; j < 9; j++)    // k' = j*64 + ci
        g_wb2[co * KTOT + j * 64 + t] = __float2bfloat16(w[co * KTOT + t * 9 + j]);
    out[t * COUT + co] = 0.0f;     // zero out[b=t][co]
}

// ---------------- main implicit-GEMM kernel ----------------
// CTA tile: M128 (one oh row) x N128; 4 warps, warp tile 64x64.
// A smem: 144-row slab per kh (2-slot ring) -- kw handled by sliding the
// ldsm base one 128B row per kw step (swizzle key shifts to (lane+kw)&7).
// B smem: [n][k] 128B rows, 3-slot ring. XOR-swizzled 16B chunks both.
// Non-trans ldmatrix both operands. 2 CTAs/SM (168KB total smem).

#define ASLOT 18432        // 144 rows x 128 B
#define BSTG  16384        // 128 rows x 128 B

__device__ __forceinline__ uint32_t smem_u32(const void* p) {
    return (uint32_t)__cvta_generic_to_shared(p);
}

__device__ __forceinline__ void cp16(uint32_t dst, const void* src) {
    asm volatile("cp.async.cg.shared.global [%0], [%1], 16;\n" :: "r"(dst), "l"(src));
}

__device__ __forceinline__ void ldsm4(uint32_t& r0, uint32_t& r1, uint32_t& r2,
                                      uint32_t& r3, uint32_t addr) {
    asm volatile("ldmatrix.sync.aligned.m8n8.x4.shared.b16 {%0,%1,%2,%3}, [%4];"
                 : "=r"(r0), "=r"(r1), "=r"(r2), "=r"(r3) : "r"(addr));
}

__device__ __forceinline__ void mma16816(float c[4],
                                         uint32_t a0, uint32_t a1, uint32_t a2, uint32_t a3,
                                         uint32_t b0, uint32_t b1) {
    asm volatile("mma.sync.aligned.m16n8k16.row.col.f32.bf16.bf16.f32 "
                 "{%0,%1,%2,%3}, {%4,%5,%6,%7}, {%8,%9}, {%0,%1,%2,%3};"
                 : "+f"(c[0]), "+f"(c[1]), "+f"(c[2]), "+f"(c[3])
                 : "r"(a0), "r"(a1), "r"(a2), "r"(a3), "r"(b0), "r"(b1));
}

__device__ __forceinline__ float gelu_tanh(float x) {
    float x3 = x * x * x;
    float u = 0.7978845608028654f * fmaf(0.044715f, x3, x);
    float t;
    asm("tanh.approx.f32 %0, %1;" : "=f"(t) : "f"(u));
    return 0.5f * x * (1.0f + t);
}

__global__ void __launch_bounds__(128, 2)
conv_gemm_kernel(const float* __restrict__ bias, float* __restrict__ out) {
    extern __shared__ char dsm[];
    const uint32_t Abase = smem_u32(dsm);            // 2 x ASLOT
    const uint32_t Bbase = Abase + 2 * ASLOT;        // 3 x BSTG

    const int tid    = threadIdx.x;
    const int lane   = tid & 31;
    const int warp   = tid >> 5;     // 0..3
    const int warp_m = warp >> 1;    // 0..1 -> 64 m-rows each
    const int warp_n = warp & 1;     // 0..1 -> 64 n-cols each
    const int oh = blockIdx.x;       // one output row per CTA
    const int n0 = blockIdx.y * 128; // COUT half
    const int b  = blockIdx.z;

    // staging roles: warp writes 4 full 128B rows per instr (4-phase floor)
    const int srow = tid >> 3;       // 0..15 (rows srow + 16i)
    const int sj   = tid & 7;        // 16B chunk within row
    const uint32_t sdoff = (uint32_t)(srow * 128 + ((sj ^ (srow & 7)) << 4));

    const __nv_bfloat16* xb = g_xn + (size_t)b * HW * CIN;
    const __nv_bfloat16* wb = g_wb2 + (size_t)n0 * KTOT;

    // --- pipeline issue: B every stage; A slab only on kw==0 stages ---
    auto issue = [&](int st) {
        const int kh = (st * 11) >> 5;     // floor(st/3), st in [0,9)
        const int kw = st - kh * 3;
        const __nv_bfloat16* bsrc = wb + (size_t)srow * KTOT + st * 64 + sj * 8;
        const uint32_t bd = Bbase + (st % 3) * BSTG + sdoff;
        #pragma unroll
        for (int i = 0; i < 8; i++)        // rows srow + 16i (swizzle inv. mod 8)
            cp16(bd + i * 2048, bsrc + (size_t)i * 16 * KTOT);
        if (kw == 0) {
            const __nv_bfloat16* asrc =
                xb + ((size_t)(oh + kh) * W + srow) * CIN + sj * 8;
            const uint32_t ad = Abase + (kh & 1) * ASLOT + sdoff;
            #pragma unroll
            for (int i = 0; i < 9; i++)    // 144 rows: w = srow + 16i
                cp16(ad + i * 2048, asrc + (size_t)i * 16 * CIN);
        }
        asm volatile("cp.async.commit_group;" ::: "memory");
    };

    issue(0); issue(1);

    float acc[4][8][4];
    #pragma unroll
    for (int a = 0; a < 4; a++)
        #pragma unroll
        for (int c = 0; c < 8; c++)
            #pragma unroll
            for (int d = 0; d < 4; d++) acc[a][c][d] = 0.0f;

    // ldmatrix lane addressing (constant per lane)
    const uint32_t a_lrow = (uint32_t)((warp_m * 64 + (lane & 15)) * 128);
    const uint32_t a_kh   = (uint32_t)(lane >> 4);                 // 0/1
    const uint32_t b_lrow = (uint32_t)((warp_n * 64 + (lane & 7) + ((lane & 16) >> 1)) * 128);
    const uint32_t b_kh   = (uint32_t)((lane >> 3) & 1);           // 0/1
    const uint32_t swzb   = (uint32_t)(lane & 7);

    // double-buffered fragments (2 x 32 regs)
    uint32_t afr[2][4][4];
    uint32_t bfr[2][8][2];

    #pragma unroll
    for (int st = 0; st < NSTG; st++) {
        if (st < NSTG - 2) asm volatile("cp.async.wait_group 1;" ::: "memory");
        else               asm volatile("cp.async.wait_group 0;" ::: "memory");
        __syncthreads();

        const int kh = (st * 11) >> 5;
        const int kw = st - kh * 3;
        // A base slides kw rows; swizzle key follows physical row parity
        const uint32_t swza   = (uint32_t)((lane + kw) & 7);
        const uint32_t a_base = Abase + (kh & 1) * ASLOT + a_lrow + (uint32_t)(kw * 128);
        const uint32_t b_base = Bbase + (st % 3) * BSTG + b_lrow;

        // slice-0 fragments FIRST (tensor pipe restarts ASAP) ...
        {
            const uint32_t ach = ((0 + a_kh) ^ swza) << 4;
            const uint32_t bch = ((0 + b_kh) ^ swzb) << 4;
            #pragma unroll
            for (int mi = 0; mi < 4; mi++)
                ldsm4(afr[0][mi][0], afr[0][mi][1], afr[0][mi][2], afr[0][mi][3],
                      a_base + (uint32_t)(mi * 2048) + ach);
            #pragma unroll
            for (int q = 0; q < 4; q++)
                ldsm4(bfr[0][2*q][0], bfr[0][2*q][1], bfr[0][2*q+1][0], bfr[0][2*q+1][1],
                      b_base + (uint32_t)(q * 2048) + bch);
        }
        // ... then the non-urgent cp.async for stage st+2
        if (st + 2 < NSTG) issue(st + 2);

        // pipelined slices: ldsm(sl+1) before mma(sl)
        #pragma unroll
        for (int sl = 0; sl < 4; sl++) {
            const int cur = sl & 1, nxt = cur ^ 1;
            if (sl < 3) {
                const uint32_t ach = (((uint32_t)(sl + 1) * 2 + a_kh) ^ swza) << 4;
                const uint32_t bch = (((uint32_t)(sl + 1) * 2 + b_kh) ^ swzb) << 4;
                #pragma unroll
                for (int mi = 0; mi < 4; mi++)
                    ldsm4(afr[nxt][mi][0], afr[nxt][mi][1], afr[nxt][mi][2], afr[nxt][mi][3],
                          a_base + (uint32_t)(mi * 2048) + ach);
                #pragma unroll
                for (int q = 0; q < 4; q++)
                    ldsm4(bfr[nxt][2*q][0], bfr[nxt][2*q][1],
                          bfr[nxt][2*q+1][0], bfr[nxt][2*q+1][1],
                          b_base + (uint32_t)(q * 2048) + bch);
            }
            #pragma unroll
            for (int mi = 0; mi < 4; mi++)
                #pragma unroll
                for (int ni = 0; ni < 8; ni++)
                    mma16816(acc[mi][ni],
                             afr[cur][mi][0], afr[cur][mi][1],
                             afr[cur][mi][2], afr[cur][mi][3],
                             bfr[cur][ni][0], bfr[cur][ni][1]);
        }
    }

    // ---- epilogue: bias + GELU + row-mean partial reduction ----
    const int group = lane >> 2;
    const int tid4  = lane & 3;

    float bcol[16];
    #pragma unroll
    for (int j = 0; j < 16; j++) {
        int ni = j >> 1, bs = j & 1;
        bcol[j] = bias[n0 + warp_n * 64 + ni * 8 + tid4 * 2 + bs];
    }

    float csum[16];
    #pragma unroll
    for (int j = 0; j < 16; j++) csum[j] = 0.0f;

    #pragma unroll
    for (int mi = 0; mi < 4; mi++) {
        #pragma unroll
        for (int half = 0; half < 2; half++) {
            int ow = warp_m * 64 + mi * 16 + half * 8 + group;
            bool ok = (ow < OW);
            #pragma unroll
            for (int ni = 0; ni < 8; ni++) {
                #pragma unroll
                for (int bs = 0; bs < 2; bs++) {
                    if (ok) {
                        float y = acc[mi][ni][half * 2 + bs] + bcol[ni * 2 + bs];
                        csum[ni * 2 + bs] += gelu_tanh(y);
                    }
                }
            }
        }
    }

    // reduce over the 8 lane-groups holding the same columns
    #pragma unroll
    for (int j = 0; j < 16; j++) {
        csum[j] += __shfl_xor_sync(0xffffffffu, csum[j], 16);
        csum[j] += __shfl_xor_sync(0xffffffffu, csum[j], 8);
        csum[j] += __shfl_xor_sync(0xffffffffu, csum[j], 4);
    }

    if (lane < 4) {
        const float inv = 1.0f / (float)MTOT;
        #pragma unroll
        for (int j = 0; j < 16; j++) {
            int ni = j >> 1, bs = j & 1;
            int n = n0 + warp_n * 64 + ni * 8 + tid4 * 2 + bs;
            atomicAdd(&out[b * COUT + n], csum[j] * inv);
        }
    }
}

// ---------------- launch ----------------

#define DSMEM_BYTES (2 * ASLOT + 3 * BSTG)   // 86016 -> 2 CTAs/SM (168KB)

extern "C" void kernel_launch(void* const* d_in, const int* in_sizes, int n_in,
                              void* d_out, int out_size) {
    const float* x    = (const float*)d_in[0];   // [64,64,128,128]
    const float* w    = (const float*)d_in[1];   // [256,64,3,3]
    const float* bias = (const float*)d_in[2];   // [256]
    float* out = (float*)d_out;                  // [64,256]

    cudaFuncSetAttribute(conv_gemm_kernel,
                         cudaFuncAttributeMaxDynamicSharedMemorySize, DSMEM_BYTES);

    // 1) x -> NHWC bf16 single copy (direct gather, no smem transpose)
    cvt_nhwc_kernel<<<dim3(H, BATCH), 256>>>(x);
    // 2) weights -> bf16 n-major rows [co][k']; zero output accumulator
    cvt_w_zero_kernel<<<COUT, 64>>>(w, out);
    // 3) fused implicit-GEMM conv + bias + GELU + mean-pool
    dim3 grid(OH, 2, BATCH);    // (126, 2 n-halves, 64)
    conv_gemm_kernel<<<grid, 128, DSMEM_BYTES>>>(bias, out);
}

// round 17
// speedup vs baseline: 1.0394x; 1.0394x over previous
#include <cuda_runtime.h>
#include <cuda_bf16.h>
#include <cstdint>

// Problem constants
#define BATCH 64
#define CIN   64
#define H     128
#define W     128
#define HW    (H*W)
#define COUT  256
#define OH    126
#define OW    126
#define MTOT  (OH*OW)     // 15876
#define KTOT  (CIN*9)     // 576
#define NSTG  9           // 9 stages of K=64 (one per (kh,kw))

// Scratch (__device__ globals: allocation-free; zero-initialized pad)
// x in NHWC bf16: g_xn[b][h][w][ci]; +256 elems pad for edge-row overreads
__device__ __align__(16) __nv_bfloat16 g_xn[(size_t)BATCH*H*W*CIN + 256];
// weights bf16, n-major K-reordered rows: g_wb2[co][k'], k' = (kh*3+kw)*64 + ci
__device__ __align__(16) __nv_bfloat16 g_wb2[COUT*KTOT];

// ---------------- prologue kernels ----------------

__global__ void cvt_nhwc_kernel(const float* __restrict__ x) {
    // direct NCHW->NHWC gather: one block per (h, b); no smem transpose
    const int h = blockIdx.x, b = blockIdx.y, tid = threadIdx.x;
    const float* src = x + (size_t)b * CIN * HW + (size_t)h * W;
    __nv_bfloat16* dst = g_xn + ((size_t)(b * H + h) * W) * CIN;
    #pragma unroll
    for (int i = 0; i < 4; i++) {
        int idx = tid + i * 256;          // 1024 uint4 chunks
        int w = idx >> 3, c0 = (idx & 7) * 8;
        uint32_t r[4];
        #pragma unroll
        for (int j = 0; j < 4; j++) {
            float lo = src[(size_t)(c0 + 2 * j)     * HW + w];
            float hi = src[(size_t)(c0 + 2 * j + 1) * HW + w];
            __nv_bfloat162 p = __floats2bfloat162_rn(lo, hi);
            r[j] = *reinterpret_cast<uint32_t*>(&p);
        }
        *reinterpret_cast<uint4*>(dst + (size_t)w * CIN + c0) =
            make_uint4(r[0], r[1], r[2], r[3]);
    }
}

// weights reorder (n-major rows) + output zero in one launch
__global__ void cvt_w_zero_kernel(const float* __restrict__ w, float* __restrict__ out) {
    const int co = blockIdx.x;     // 0..255
    const int t  = threadIdx.x;    // 0..63 (= ci)
    #pragma unroll
    for (int j = 0; j < 9; j++)    // k' = j*64 + ci
        g_wb2[co * KTOT + j * 64 + t] = __float2bfloat16(w[co * KTOT + t * 9 + j]);
    out[t * COUT + co] = 0.0f;     // zero out[b=t][co]
}

// ---------------- main implicit-GEMM kernel (R15 — measured 610us) ----------------
// CTA tile: M128 (one oh row) x N128; 4 warps, warp tile 64x64.
// A smem [m][k] bf16 128B rows, B smem [n][k] bf16 128B rows, both with
// XOR-swizzled 16B chunks (chunk ^ (row&7)). Non-trans ldmatrix for both.
// K=64 stages (one (kh,kw) each); STG=3 ring; 2 CTAs/SM (196KB total smem).

#define STG 3
#define ASTG 16384     // 128 rows x 128 B
#define BSTG 16384

__device__ __forceinline__ uint32_t smem_u32(const void* p) {
    return (uint32_t)__cvta_generic_to_shared(p);
}

__device__ __forceinline__ void cp16(uint32_t dst, const void* src) {
    asm volatile("cp.async.cg.shared.global [%0], [%1], 16;\n" :: "r"(dst), "l"(src));
}

__device__ __forceinline__ void ldsm4(uint32_t& r0, uint32_t& r1, uint32_t& r2,
                                      uint32_t& r3, uint32_t addr) {
    asm volatile("ldmatrix.sync.aligned.m8n8.x4.shared.b16 {%0,%1,%2,%3}, [%4];"
                 : "=r"(r0), "=r"(r1), "=r"(r2), "=r"(r3) : "r"(addr));
}

__device__ __forceinline__ void mma16816(float c[4],
                                         uint32_t a0, uint32_t a1, uint32_t a2, uint32_t a3,
                                         uint32_t b0, uint32_t b1) {
    asm volatile("mma.sync.aligned.m16n8k16.row.col.f32.bf16.bf16.f32 "
                 "{%0,%1,%2,%3}, {%4,%5,%6,%7}, {%8,%9}, {%0,%1,%2,%3};"
                 : "+f"(c[0]), "+f"(c[1]), "+f"(c[2]), "+f"(c[3])
                 : "r"(a0), "r"(a1), "r"(a2), "r"(a3), "r"(b0), "r"(b1));
}

__device__ __forceinline__ float gelu_tanh(float x) {
    float x3 = x * x * x;
    float u = 0.7978845608028654f * fmaf(0.044715f, x3, x);
    float t;
    asm("tanh.approx.f32 %0, %1;" : "=f"(t) : "f"(u));
    return 0.5f * x * (1.0f + t);
}

__global__ void __launch_bounds__(128, 2)
conv_gemm_kernel(const float* __restrict__ bias, float* __restrict__ out) {
    extern __shared__ char dsm[];
    const uint32_t Abase = smem_u32(dsm);
    const uint32_t Bbase = Abase + STG * ASTG;

    const int tid    = threadIdx.x;
    const int lane   = tid & 31;
    const int warp   = tid >> 5;     // 0..3
    const int warp_m = warp >> 1;    // 0..1 -> 64 m-rows each
    const int warp_n = warp & 1;     // 0..1 -> 64 n-cols each
    const int oh = blockIdx.x;       // one output row per CTA
    const int n0 = blockIdx.y * 128; // COUT half
    const int b  = blockIdx.z;

    // staging roles: warp writes 4 full 128B rows per instr (4-phase floor)
    const int srow = tid >> 3;       // 0..15 (rows srow + 16i)
    const int sj   = tid & 7;        // 16B chunk within row
    const uint32_t sdoff = (uint32_t)(srow * 128 + ((sj ^ (srow & 7)) << 4));

    const __nv_bfloat16* xb = g_xn + (size_t)b * HW * CIN;
    const __nv_bfloat16* wb = g_wb2 + (size_t)n0 * KTOT;

    // --- pipeline issue: one stage = K64 = one (kh,kw), ci 0..63 ---
    auto issue = [&](int st) {
        const int slot = st % STG;
        const int kh = (st * 11) >> 5;     // floor(st/3), st in [0,9)
        const int kw = st - kh * 3;
        const __nv_bfloat16* asrc =
            xb + ((size_t)(oh + kh) * W + srow + kw) * CIN + sj * 8;
        const __nv_bfloat16* bsrc = wb + (size_t)srow * KTOT + st * 64 + sj * 8;
        const uint32_t ad = Abase + slot * ASTG + sdoff;
        const uint32_t bd = Bbase + slot * BSTG + sdoff;
        #pragma unroll
        for (int i = 0; i < 8; i++) {      // rows srow + 16i  (swizzle invariant mod 8)
            cp16(ad + i * 2048, asrc + (size_t)i * 16 * CIN);
            cp16(bd + i * 2048, bsrc + (size_t)i * 16 * KTOT);
        }
        asm volatile("cp.async.commit_group;" ::: "memory");
    };

    issue(0); issue(1);

    float acc[4][8][4];
    #pragma unroll
    for (int a = 0; a < 4; a++)
        #pragma unroll
        for (int c = 0; c < 8; c++)
            #pragma unroll
            for (int d = 0; d < 4; d++) acc[a][c][d] = 0.0f;

    // ldmatrix lane addressing (constant per lane), XOR swizzle = lane&7
    const uint32_t swz    = (uint32_t)(lane & 7);
    const uint32_t a_lrow = (uint32_t)((warp_m * 64 + (lane & 15)) * 128);
    const uint32_t a_kh   = (uint32_t)(lane >> 4);                 // 0/1
    const uint32_t b_lrow = (uint32_t)((warp_n * 64 + (lane & 7) + ((lane & 16) >> 1)) * 128);
    const uint32_t b_kh   = (uint32_t)((lane >> 3) & 1);           // 0/1

    // double-buffered fragments (2 x 32 regs)
    uint32_t afr[2][4][4];
    uint32_t bfr[2][8][2];

    #pragma unroll
    for (int st = 0; st < NSTG; st++) {
        if (st < NSTG - 2) asm volatile("cp.async.wait_group 1;" ::: "memory");
        else               asm volatile("cp.async.wait_group 0;" ::: "memory");
        __syncthreads();

        const int slot = st % STG;
        const uint32_t a_base = Abase + slot * ASTG + a_lrow;
        const uint32_t b_base = Bbase + slot * BSTG + b_lrow;

        // slice-0 fragments FIRST (tensor pipe restarts ASAP) ...
        {
            const uint32_t ach = ((0 + a_kh) ^ swz) << 4;
            const uint32_t bch = ((0 + b_kh) ^ swz) << 4;
            #pragma unroll
            for (int mi = 0; mi < 4; mi++)
                ldsm4(afr[0][mi][0], afr[0][mi][1], afr[0][mi][2], afr[0][mi][3],
                      a_base + (uint32_t)(mi * 2048) + ach);
            #pragma unroll
            for (int q = 0; q < 4; q++)
                ldsm4(bfr[0][2*q][0], bfr[0][2*q][1], bfr[0][2*q+1][0], bfr[0][2*q+1][1],
                      b_base + (uint32_t)(q * 2048) + bch);
        }
        // ... then the non-urgent cp.async for stage st+2 (slot (st+2)%3 != st%3)
        if (st + 2 < NSTG) issue(st + 2);

        // pipelined slices: ldsm(sl+1) before mma(sl)
        #pragma unroll
        for (int sl = 0; sl < 4; sl++) {
            const int cur = sl & 1, nxt = cur ^ 1;
            if (sl < 3) {
                const uint32_t ach = (((uint32_t)(sl + 1) * 2 + a_kh) ^ swz) << 4;
                const uint32_t bch = (((uint32_t)(sl + 1) * 2 + b_kh) ^ swz) << 4;
                #pragma unroll
                for (int mi = 0; mi < 4; mi++)
                    ldsm4(afr[nxt][mi][0], afr[nxt][mi][1], afr[nxt][mi][2], afr[nxt][mi][3],
                          a_base + (uint32_t)(mi * 2048) + ach);
                #pragma unroll
                for (int q = 0; q < 4; q++)
                    ldsm4(bfr[nxt][2*q][0], bfr[nxt][2*q][1],
                          bfr[nxt][2*q+1][0], bfr[nxt][2*q+1][1],
                          b_base + (uint32_t)(q * 2048) + bch);
            }
            #pragma unroll
            for (int mi = 0; mi < 4; mi++)
                #pragma unroll
                for (int ni = 0; ni < 8; ni++)
                    mma16816(acc[mi][ni],
                             afr[cur][mi][0], afr[cur][mi][1],
                             afr[cur][mi][2], afr[cur][mi][3],
                             bfr[cur][ni][0], bfr[cur][ni][1]);
        }
    }

    // ---- epilogue: bias + GELU + row-mean partial reduction ----
    const int group = lane >> 2;
    const int tid4  = lane & 3;

    float bcol[16];
    #pragma unroll
    for (int j = 0; j < 16; j++) {
        int ni = j >> 1, bs = j & 1;
        bcol[j] = bias[n0 + warp_n * 64 + ni * 8 + tid4 * 2 + bs];
    }

    float csum[16];
    #pragma unroll
    for (int j = 0; j < 16; j++) csum[j] = 0.0f;

    #pragma unroll
    for (int mi = 0; mi < 4; mi++) {
        #pragma unroll
        for (int half = 0; half < 2; half++) {
            int ow = warp_m * 64 + mi * 16 + half * 8 + group;
            bool ok = (ow < OW);
            #pragma unroll
            for (int ni = 0; ni < 8; ni++) {
                #pragma unroll
                for (int bs = 0; bs < 2; bs++) {
                    if (ok) {
                        float y = acc[mi][ni][half * 2 + bs] + bcol[ni * 2 + bs];
                        csum[ni * 2 + bs] += gelu_tanh(y);
                    }
                }
            }
        }
    }

    // reduce over the 8 lane-groups holding the same columns
    #pragma unroll
    for (int j = 0; j < 16; j++) {
        csum[j] += __shfl_xor_sync(0xffffffffu, csum[j], 16);
        csum[j] += __shfl_xor_sync(0xffffffffu, csum[j], 8);
        csum[j] += __shfl_xor_sync(0xffffffffu, csum[j], 4);
    }

    if (lane < 4) {
        const float inv = 1.0f / (float)MTOT;
        #pragma unroll
        for (int j = 0; j < 16; j++) {
            int ni = j >> 1, bs = j & 1;
            int n = n0 + warp_n * 64 + ni * 8 + tid4 * 2 + bs;
            atomicAdd(&out[b * COUT + n], csum[j] * inv);
        }
    }
}

// ---------------- launch ----------------

#define DSMEM_BYTES (STG * (ASTG + BSTG))   // 98304 -> 2 CTAs/SM (196KB)

extern "C" void kernel_launch(void* const* d_in, const int* in_sizes, int n_in,
                              void* d_out, int out_size) {
    const float* x    = (const float*)d_in[0];   // [64,64,128,128]
    const float* w    = (const float*)d_in[1];   // [256,64,3,3]
    const float* bias = (const float*)d_in[2];   // [256]
    float* out = (float*)d_out;                  // [64,256]

    cudaFuncSetAttribute(conv_gemm_kernel,
                         cudaFuncAttributeMaxDynamicSharedMemorySize, DSMEM_BYTES);

    // 1) x -> NHWC bf16 single copy (direct gather, no smem transpose)
    cvt_nhwc_kernel<<<dim3(H, BATCH), 256>>>(x);
    // 2) weights -> bf16 n-major rows [co][k']; zero output accumulator
    cvt_w_zero_kernel<<<COUT, 64>>>(w, out);
    // 3) fused implicit-GEMM conv + bias + GELU + mean-pool
    dim3 grid(OH, 2, BATCH);    // (126, 2 n-halves, 64)
    conv_gemm_kernel<<<grid, 128, DSMEM_BYTES>>>(bias, out);
}